// round 17
// baseline (speedup 1.0000x reference)
#include <cuda_runtime.h>
#include <cuda_fp16.h>
#include <math.h>
#include <stdint.h>

#define D_MODEL 512
#define D_FF    2048
#define GKN     8
#define NTOK    4096

// fp16 K-concat layouts:
//  layer1 activations: [bases(4096) | S(512)]    strideK=4608
//  layer2 activations: [bases(16384)| S(2048)]   strideK=18432
#define K1P (D_MODEL * GKN + D_MODEL)   // 4608
#define K2P (D_FF * GKN + D_FF)         // 18432

__device__ __half g_A1[(size_t)NTOK * K1P];
__device__ __half g_A2[(size_t)NTOK * K2P];
__device__ __half g_W1[(size_t)D_FF * K1P];
__device__ __half g_W2[(size_t)D_MODEL * K2P];

// producer->consumer flags (re-zeroed by prep_kernel each launch)
__device__ int g_flag[32];
__device__ int g_auxflag;

// ---------------------------------------------------------------------------
// PTX helpers (arch-agnostic on .target sm_103)
// ---------------------------------------------------------------------------
__device__ __forceinline__ uint32_t cvta_smem(const void* p) {
    uint32_t a;
    asm("{ .reg .u64 t; cvta.to.shared.u64 t, %1; cvt.u32.u64 %0, t; }" : "=r"(a) : "l"(p));
    return a;
}
__device__ __forceinline__ void cp16(uint32_t s, const void* g) {
    asm volatile("cp.async.cg.shared.global [%0], [%1], 16;" :: "r"(s), "l"(g));
}
__device__ __forceinline__ void cp_commit() {
    asm volatile("cp.async.commit_group;" ::: "memory");
}
template <int N>
__device__ __forceinline__ void cp_wait() {
    asm volatile("cp.async.wait_group %0;" :: "n"(N) : "memory");
}
__device__ __forceinline__ void ldmx4(uint32_t* r, uint32_t a) {
    asm volatile("ldmatrix.sync.aligned.m8n8.x4.shared.b16 {%0,%1,%2,%3}, [%4];"
                 : "=r"(r[0]), "=r"(r[1]), "=r"(r[2]), "=r"(r[3]) : "r"(a));
}
__device__ __forceinline__ void mma16816(float* d, const uint32_t* a, uint32_t b0, uint32_t b1) {
    asm volatile(
        "mma.sync.aligned.m16n8k16.row.col.f32.f16.f16.f32 "
        "{%0,%1,%2,%3}, {%4,%5,%6,%7}, {%8,%9}, {%0,%1,%2,%3};"
        : "+f"(d[0]), "+f"(d[1]), "+f"(d[2]), "+f"(d[3])
        : "r"(a[0]), "r"(a[1]), "r"(a[2]), "r"(a[3]), "r"(b0), "r"(b1));
}

// ---------------------------------------------------------------------------
// Closed-form uniform cubic B-spline expansion (cardinal N3 translates).
// ---------------------------------------------------------------------------
__device__ __forceinline__ void expand_one(float v, float t0, float ih,
                                           __half& s16, uint4& pk) {
    float s = v * __fdividef(1.0f, 1.0f + __expf(-v));
    s16 = __float2half_rn(s);

    float u = (v - t0) * ih;
    float jf = floorf(u);
    int j0 = (int)jf;
    float w = u - jf;
    float w2 = w * w, w3 = w2 * w;
    const float k6 = 1.0f / 6.0f;
    float c3 = w3 * k6;
    float c2 = k6 * (1.0f + 3.0f * w + 3.0f * w2 - 3.0f * w3);
    float c1 = k6 * (4.0f - 6.0f * w2 + 3.0f * w3);
    float c0 = k6 * (1.0f - 3.0f * w + 3.0f * w2 - w3);

    float bq[8];
#pragma unroll
    for (int q = 0; q < 8; q++) {
        int d = j0 - q;
        float val = 0.0f;
        val = (d == 0) ? c3 : val;
        val = (d == 1) ? c2 : val;
        val = (d == 2) ? c1 : val;
        val = (d == 3) ? c0 : val;
        bq[q] = val;
    }

    __half2 p0 = __floats2half2_rn(bq[0], bq[1]);
    __half2 p1 = __floats2half2_rn(bq[2], bq[3]);
    __half2 p2 = __floats2half2_rn(bq[4], bq[5]);
    __half2 p3 = __floats2half2_rn(bq[6], bq[7]);
    pk.x = *(uint32_t*)&p0; pk.y = *(uint32_t*)&p1;
    pk.z = *(uint32_t*)&p2; pk.w = *(uint32_t*)&p3;
}

// ---------------------------------------------------------------------------
// Per-element job bodies
// ---------------------------------------------------------------------------
__device__ __forceinline__ void do_expand(const float* __restrict__ x,
                                          float t0, float ih,
                                          __half* __restrict__ pA,
                                          int idx, int in_log2, int strideK) {
    const int IN = 1 << in_log2;
    const int row = idx >> in_log2;
    const int i = idx & (IN - 1);

    __half s16;
    uint4 pk;
    expand_one(x[idx], t0, ih, s16, pk);

    __half* rowp = pA + (size_t)row * strideK;
    *(uint4*)(rowp + i * 8) = pk;
    rowp[IN * 8 + i] = s16;
}

__device__ __forceinline__ void do_pack_w(const float* __restrict__ wb,
                                          const float* __restrict__ ws,
                                          __half* __restrict__ pW,
                                          int idx, int in_log2, int strideK) {
    const int IN = 1 << in_log2;
    const int o = idx >> in_log2;
    const int i = idx & (IN - 1);

    float4 s0 = ((const float4*)ws)[idx * 2];
    float4 s1 = ((const float4*)ws)[idx * 2 + 1];
    __half2 p0 = __floats2half2_rn(s0.x, s0.y);
    __half2 p1 = __floats2half2_rn(s0.z, s0.w);
    __half2 p2 = __floats2half2_rn(s1.x, s1.y);
    __half2 p3 = __floats2half2_rn(s1.z, s1.w);
    uint4 pk;
    pk.x = *(uint32_t*)&p0; pk.y = *(uint32_t*)&p1;
    pk.z = *(uint32_t*)&p2; pk.w = *(uint32_t*)&p3;

    __half* rowp = pW + (size_t)o * strideK;
    *(uint4*)(rowp + i * 8) = pk;
    rowp[IN * 8 + i] = __float2half_rn(wb[idx]);
}

// ---------------------------------------------------------------------------
// Preprocessing before mega kernel: pack W1, expand layer-1 input, zero flags.
// ---------------------------------------------------------------------------
#define NB1 (D_FF * D_MODEL / 256)           // 4096
#define NB3 (NTOK * D_MODEL / 256)           // 8192

__global__ void __launch_bounds__(256)
prep_kernel(const float* __restrict__ x, const float* __restrict__ grid,
            const float* __restrict__ w1b, const float* __restrict__ w1s,
            __half* __restrict__ W1, __half* __restrict__ A1) {
    const int b = blockIdx.x;
    if (b == 0 && threadIdx.x < 33) {
        if (threadIdx.x < 32) g_flag[threadIdx.x] = 0;
        else g_auxflag = 0;
    }
    if (b < NB1) {
        int idx = b * 256 + threadIdx.x;
        do_pack_w(w1b, w1s, W1, idx, 9, K1P);
    } else {
        int idx = (b - NB1) * 256 + threadIdx.x;
        const float t0 = __ldg(grid);
        const float ih = __fdividef(1.0f, __ldg(grid + 1) - t0);
        do_expand(x, t0, ih, A1, idx, 9, K1P);
    }
}

// ---------------------------------------------------------------------------
// GEMM body (device function): C(M,Nout) (+)= A(.,K) * B(.,K)^T, fp32 acc.
// Warp grid WR x WC (256 threads), warp tile (MI*16) x (NI*8). BK=64,
// 3-stage cp.async, one __syncthreads per K-iter, frag double-buffering.
// SPLITK: kidx selects K-half, atomicAdd epilogue (C pre-zeroed).
// KAN: fused layer-2 expansion epilogue (coalesced A2 stores).
// ---------------------------------------------------------------------------
#define BKK 64
#define STAGES 3
#define LDT 72
#define HS 260

template <int WR, int WC, int MI, int NI, bool SPLITK, bool KAN>
__device__ __forceinline__ void gemm_body(
    const __half* __restrict__ A, const __half* __restrict__ B,
    float* __restrict__ C, __half* __restrict__ A2,
    const float* __restrict__ gridk, int Nout, int K,
    int m0, int n0, int kidx) {
    constexpr int THREADS = WR * WC * 32;
    constexpr int NWARP = WR * WC;
    constexpr int BM_ = WR * MI * 16;
    constexpr int BN_ = WC * NI * 8;
    constexpr int TILE_A = BM_ * LDT;
    constexpr int TILE_B = BN_ * LDT;
    constexpr int RP = THREADS / 8;
    extern __shared__ __half sm[];
    const uint32_t sm_base = cvta_smem(sm);

    const int tid = threadIdx.x;
    const int lane = tid & 31;
    const int wid = tid >> 5;
    const int wm = wid / WC;
    const int wn = wid % WC;

    const int kseg = SPLITK ? (K >> 1) : K;
    const size_t koff0 = SPLITK ? (size_t)kidx * kseg : 0;

    const __half* Ag = A + (size_t)m0 * K + koff0;
    const __half* Bg = B + (size_t)n0 * K + koff0;

    const int lrow = tid >> 3;
    const int lcol = (tid & 7) * 8;

    const int nk = kseg / BKK;

    auto stage_load = [&](int ks) {
        const int buf = ks % STAGES;
        const size_t koff = (size_t)ks * BKK + lcol;
        const uint32_t abase = sm_base + (uint32_t)(buf * (TILE_A + TILE_B)) * 2;
        const uint32_t bbase = abase + (uint32_t)TILE_A * 2;
#pragma unroll
        for (int r = 0; r < BM_; r += RP)
            cp16(abase + (uint32_t)((lrow + r) * LDT + lcol) * 2,
                 Ag + (size_t)(lrow + r) * K + koff);
#pragma unroll
        for (int r = 0; r < BN_; r += RP)
            cp16(bbase + (uint32_t)((lrow + r) * LDT + lcol) * 2,
                 Bg + (size_t)(lrow + r) * K + koff);
        cp_commit();
    };

    float acc[MI][NI][4];
#pragma unroll
    for (int i = 0; i < MI; i++)
#pragma unroll
        for (int j = 0; j < NI; j++)
#pragma unroll
            for (int e = 0; e < 4; e++) acc[i][j][e] = 0.0f;

    const int lm_row = lane & 15;
    const int lm_koff = (lane >> 4) * 8;

    uint32_t afr[2][MI][4];
    uint32_t bfr[2][NI / 2][4];

    stage_load(0);
    stage_load(1);

    for (int ks = 0; ks < nk; ks++) {
        if (ks + 1 < nk) cp_wait<1>(); else cp_wait<0>();
        __syncthreads();
        if (ks + 2 < nk) stage_load(ks + 2);

        const int buf = ks % STAGES;
        const uint32_t abase = sm_base + (uint32_t)(buf * (TILE_A + TILE_B)) * 2 +
                               (uint32_t)((wm * MI * 16 + lm_row) * LDT + lm_koff) * 2;
        const uint32_t bbase = sm_base + (uint32_t)(buf * (TILE_A + TILE_B) + TILE_A) * 2 +
                               (uint32_t)((wn * NI * 8 + lm_row) * LDT + lm_koff) * 2;

#pragma unroll
        for (int mi = 0; mi < MI; mi++)
            ldmx4(afr[0][mi], abase + (uint32_t)(mi * 16 * LDT) * 2);
#pragma unroll
        for (int g = 0; g < NI / 2; g++)
            ldmx4(bfr[0][g], bbase + (uint32_t)(g * 16 * LDT) * 2);

#pragma unroll
        for (int kf = 0; kf < 4; kf++) {
            const int cur = kf & 1, nxt = cur ^ 1;
            if (kf < 3) {
                const uint32_t ka = abase + (uint32_t)((kf + 1) * 16) * 2;
                const uint32_t kb = bbase + (uint32_t)((kf + 1) * 16) * 2;
#pragma unroll
                for (int mi = 0; mi < MI; mi++)
                    ldmx4(afr[nxt][mi], ka + (uint32_t)(mi * 16 * LDT) * 2);
#pragma unroll
                for (int g = 0; g < NI / 2; g++)
                    ldmx4(bfr[nxt][g], kb + (uint32_t)(g * 16 * LDT) * 2);
            }
#pragma unroll
            for (int mi = 0; mi < MI; mi++)
#pragma unroll
                for (int ni = 0; ni < NI; ni++) {
                    const int g = ni >> 1, o = ni & 1;
                    mma16816(acc[mi][ni], afr[cur][mi], bfr[cur][g][o], bfr[cur][g][o + 2]);
                }
        }
    }

    const int erow = lane >> 2;
    const int ecol = (lane & 3) * 2;

    if (KAN) {
        __syncthreads();
        float* hs = reinterpret_cast<float*>(sm);
#pragma unroll
        for (int mi = 0; mi < MI; mi++)
#pragma unroll
            for (int ni = 0; ni < NI; ni++) {
                const int r = wm * MI * 16 + mi * 16 + erow;
                const int c = wn * NI * 8 + ni * 8 + ecol;
                hs[r * HS + c]           = acc[mi][ni][0];
                hs[r * HS + c + 1]       = acc[mi][ni][1];
                hs[(r + 8) * HS + c]     = acc[mi][ni][2];
                hs[(r + 8) * HS + c + 1] = acc[mi][ni][3];
            }
        __syncthreads();

        const float t0 = __ldg(gridk);
        const float ih = __fdividef(1.0f, __ldg(gridk + 1) - t0);
        const int off = D_FF * 8;
        for (int r = wid; r < BM_; r += NWARP) {
            __half* rowp = A2 + (size_t)(m0 + r) * K2P;
#pragma unroll
            for (int c0 = 0; c0 < BN_; c0 += 32) {
                float v = hs[r * HS + c0 + lane];
                __half s16;
                uint4 pk;
                expand_one(v, t0, ih, s16, pk);
                const int gc = n0 + c0 + lane;
                *(uint4*)(rowp + gc * 8) = pk;
                rowp[off + gc] = s16;
            }
        }
    } else {
#pragma unroll
        for (int mi = 0; mi < MI; mi++) {
#pragma unroll
            for (int ni = 0; ni < NI; ni++) {
                const int row = m0 + wm * MI * 16 + mi * 16 + erow;
                const int col = n0 + wn * NI * 8 + ni * 8 + ecol;
                float* p0 = C + (size_t)row * Nout + col;
                float* p1 = C + (size_t)(row + 8) * Nout + col;
                if (SPLITK) {
                    atomicAdd(p0,     acc[mi][ni][0]);
                    atomicAdd(p0 + 1, acc[mi][ni][1]);
                    atomicAdd(p1,     acc[mi][ni][2]);
                    atomicAdd(p1 + 1, acc[mi][ni][3]);
                } else {
                    *(float2*)p0 = make_float2(acc[mi][ni][0], acc[mi][ni][1]);
                    *(float2*)p1 = make_float2(acc[mi][ni][2], acc[mi][ni][3]);
                }
            }
        }
    }
}

// ---------------------------------------------------------------------------
// Mega kernel: gemm1 (bids 0-255) -> flags; aux (256-319) pack W2 + zero out;
// gemm2 (320-575) waits on flags then computes out.
// ---------------------------------------------------------------------------
#define NAUX 64

__global__ void __launch_bounds__(256, 1)
mega_kernel(const __half* __restrict__ A1, const __half* __restrict__ W1,
            __half* __restrict__ A2, __half* __restrict__ W2p,
            float* __restrict__ out, const float* __restrict__ grid,
            const float* __restrict__ w2b, const float* __restrict__ w2s) {
    const int bid = blockIdx.x;
    if (bid < 256) {
        // ---- gemm1 tile: n-tile = bid&7, m-block = bid>>3 ----
        const int n0 = (bid & 7) * 256;
        const int m0 = (bid >> 3) * 128;
        gemm_body<2, 4, 4, 8, false, true>(A1, W1, nullptr, A2, grid,
                                           D_FF, K1P, m0, n0, 0);
        __threadfence();
        __syncthreads();
        if (threadIdx.x == 0) atomicAdd(&g_flag[m0 >> 7], 1);
    } else if (bid < 256 + NAUX) {
        // ---- aux: pack W2 + zero out ----
        const int aid = bid - 256;
        const int nthr = NAUX * 256;
        const int gtid = aid * 256 + threadIdx.x;
        for (int idx = gtid; idx < D_MODEL * D_FF; idx += nthr)
            do_pack_w(w2b, w2s, W2p, idx, 11, K2P);
        const float4 z = make_float4(0.f, 0.f, 0.f, 0.f);
        for (int i = gtid; i < NTOK * D_MODEL / 4; i += nthr)
            ((float4*)out)[i] = z;
        __threadfence();
        __syncthreads();
        if (threadIdx.x == 0) atomicAdd(&g_auxflag, 1);
    } else {
        // ---- gemm2 tile: ordered by m ascending to match gemm1 completion ----
        const int b2 = bid - 256 - NAUX;
        const int m = b2 >> 3;              // 0..31
        const int rem = b2 & 7;             // 4 n-tiles x 2 k-halves
        const int n0 = (rem >> 1) * 128;
        const int kh = rem & 1;
        if (threadIdx.x == 0) {
            while (*(volatile int*)&g_flag[m] < 8) __nanosleep(64);
            while (*(volatile int*)&g_auxflag < NAUX) __nanosleep(64);
        }
        __syncthreads();
        __threadfence();
        gemm_body<2, 4, 4, 4, true, false>(A2, W2p, out, nullptr, nullptr,
                                           D_MODEL, K2P, m * 128, n0, kh);
    }
}

// ---------------------------------------------------------------------------
// Launch
// ---------------------------------------------------------------------------
extern "C" void kernel_launch(void* const* d_in, const int* in_sizes, int n_in,
                              void* d_out, int out_size) {
    const float* x    = (const float*)d_in[0];
    const float* grid = (const float*)d_in[1];
    const float* w1b  = (const float*)d_in[2];
    const float* w1s  = (const float*)d_in[3];
    const float* w2b  = (const float*)d_in[4];
    const float* w2s  = (const float*)d_in[5];
    float* out = (float*)d_out;

    __half *A1, *A2, *W1, *W2;
    cudaGetSymbolAddress((void**)&A1, g_A1);
    cudaGetSymbolAddress((void**)&A2, g_A2);
    cudaGetSymbolAddress((void**)&W1, g_W1);
    cudaGetSymbolAddress((void**)&W2, g_W2);

    const int smem = STAGES * (128 + 256) * LDT * 2;  // 165888
    cudaFuncSetAttribute((const void*)mega_kernel,
                         cudaFuncAttributeMaxDynamicSharedMemorySize, smem);

    // ---- prep: pack W1, expand x -> A1, zero flags ----
    prep_kernel<<<NB1 + NB3, 256>>>(x, grid, w1b, w1s, W1, A1);

    // ---- mega: gemm1 + aux + gemm2 in one launch ----
    mega_kernel<<<256 + NAUX + 256, 256, smem>>>(A1, W1, A2, W2, out, grid,
                                                 w2b, w2s);
}